// round 16
// baseline (speedup 1.0000x reference)
#include <cuda_runtime.h>
#include <cuda_bf16.h>
#include <cstdint>

#define BB 16
#define CC 64
#define NN 2048
#define RS 144     // bf16 tile row stride (bytes): 128 data + 16 pad
#define SROW 129   // fp32 score row stride (words)

// ---------------- scratch (no allocation allowed) ----------------
__device__ __nv_bfloat16 g_hi[BB * NN * CC];   // [b][n][c]
__device__ __nv_bfloat16 g_lo[BB * NN * CC];
__device__ float         g_xx[BB * NN];
__device__ float         g_pv[(size_t)BB * NN * 16 * 9];   // partial top-9 vals
__device__ int           g_pi[(size_t)BB * NN * 16 * 9];   // partial top-9 idx
__device__ int           g_idx[BB * NN * 8];

// smem layout (bytes) — identical to R5
#define AHI 0
#define ALO (AHI + 128 * RS)       // 18432
#define BHI (ALO + 128 * RS)       // 36864
#define BLO (BHI + 128 * RS)       // 55296
#define XXA (BLO + 128 * RS)       // 73728
#define XXB (XXA + 512)            // 74240
#define SM_TOTAL (XXB + 512)       // 74752;  S[128][129] fp32 aliases [0, 66048)

__device__ __forceinline__ uint32_t smem_u32(const void* p) {
    uint32_t a;
    asm("{ .reg .u64 t; cvta.to.shared.u64 t, %1; cvt.u32.u64 %0, t; }" : "=r"(a) : "l"(p));
    return a;
}
__device__ __forceinline__ void ldsm4(uint32_t& r0, uint32_t& r1, uint32_t& r2, uint32_t& r3,
                                      uint32_t addr) {
    asm volatile("ldmatrix.sync.aligned.m8n8.x4.shared.b16 {%0,%1,%2,%3}, [%4];"
                 : "=r"(r0), "=r"(r1), "=r"(r2), "=r"(r3) : "r"(addr));
}
__device__ __forceinline__ void mma16816(float* c, const uint32_t* a, uint32_t b0, uint32_t b1) {
    asm volatile(
        "mma.sync.aligned.m16n8k16.row.col.f32.bf16.bf16.f32 "
        "{%0,%1,%2,%3}, {%4,%5,%6,%7}, {%8,%9}, {%0,%1,%2,%3};"
        : "+f"(c[0]), "+f"(c[1]), "+f"(c[2]), "+f"(c[3])
        : "r"(a[0]), "r"(a[1]), "r"(a[2]), "r"(a[3]), "r"(b0), "r"(b1));
}
__device__ __forceinline__ void cp16(uint32_t dst, const void* src) {
    asm volatile("cp.async.cg.shared.global [%0], [%1], 16;" :: "r"(dst), "l"(src));
}
#define CP_COMMIT() asm volatile("cp.async.commit_group;" ::: "memory")
#define CP_WAIT0()  asm volatile("cp.async.wait_group 0;" ::: "memory")

// lexicographic top-9 insert: (val desc, idx asc) == top_k semantics, order-free
#define INS9(v, ii)                                                            \
    if ((v) > val9[8] || ((v) == val9[8] && (ii) < idx9[8])) {                 \
        val9[8] = (v); idx9[8] = (ii);                                         \
        _Pragma("unroll")                                                      \
        for (int k = 8; k > 0; --k) {                                          \
            if (val9[k] > val9[k - 1] ||                                       \
                (val9[k] == val9[k - 1] && idx9[k] < idx9[k - 1])) {           \
                float tv = val9[k]; val9[k] = val9[k - 1]; val9[k - 1] = tv;   \
                int ti_ = idx9[k]; idx9[k] = idx9[k - 1]; idx9[k - 1] = ti_;   \
            }                                                                  \
        }                                                                      \
    }

// ---------------------------------------------------------------------------
// Prep: hi/lo bf16 split, transposed [b][n][c] + fp32 norms.  (R5 verbatim)
// ---------------------------------------------------------------------------
__global__ void prep_kernel(const float* __restrict__ x) {
    int b = blockIdx.y;
    int n = blockIdx.x * 128 + threadIdx.x;
    const float* xp = x + b * CC * NN + n;
    __nv_bfloat162 hi2[32], lo2[32];
    float s = 0.f;
#pragma unroll
    for (int c2 = 0; c2 < 32; ++c2) {
        float v0 = xp[(2 * c2) * NN];
        float v1 = xp[(2 * c2 + 1) * NN];
        s = fmaf(v0, v0, s);
        s = fmaf(v1, v1, s);
        __nv_bfloat16 h0 = __float2bfloat16(v0);
        __nv_bfloat16 h1 = __float2bfloat16(v1);
        float r0 = v0 - __bfloat162float(h0);
        float r1 = v1 - __bfloat162float(h1);
        hi2[c2] = __halves2bfloat162(h0, h1);
        lo2[c2] = __halves2bfloat162(__float2bfloat16(r0), __float2bfloat16(r1));
    }
    g_xx[b * NN + n] = s;
    size_t rowo = (size_t)(b * NN + n) * CC;
    uint4* dh = (uint4*)(g_hi + rowo);
    uint4* dl = (uint4*)(g_lo + rowo);
    const uint4* sh = (const uint4*)hi2;
    const uint4* sl = (const uint4*)lo2;
#pragma unroll
    for (int i = 0; i < 8; ++i) { dh[i] = sh[i]; dl[i] = sl[i]; }
}

// ---------------------------------------------------------------------------
// KNN: R5 tile body inside a long CTA loop.
// CTA = (batch, pair a<->15-a, half): 8 or 9 full 128x128 upper-triangle
// tiles, stateless per tile (A reloaded; lists per-tile). 256 CTAs = 1 wave,
// long CTAs de-phase co-residents (R4/R9 evidence) -> tensor pipe stays fed.
// ---------------------------------------------------------------------------
__global__ void __launch_bounds__(256, 2) knn_kernel() {
    extern __shared__ char sm[];
    const uint32_t sb = smem_u32(sm);
    const int tid  = threadIdx.x;
    const int lane = tid & 31;
    const int w    = tid >> 5;
    const int wrow = (w >> 1) * 32;       // warp query-row offset (0..96)
    const int wcol = (w & 1) * 64;        // warp candidate-col offset (0/64)
    const int b    = blockIdx.y;
    const int a    = blockIdx.x >> 1;
    const int h    = blockIdx.x & 1;
    const int nA   = 16 - a;
    const int ap   = 15 - a;
    const int Lbeg = h * 8, Lend = h ? 17 : 8;

    float* S   = (float*)sm;              // aliases A/B after MMA
    float* xxA = (float*)(sm + XXA);
    float* xxB = (float*)(sm + XXB);

    const int lrow = lane & 15;
    const int lcol = (lane >> 4) * 16;
    const uint32_t aHiB = sb + AHI + (wrow + lrow) * RS + lcol;
    const uint32_t aLoB = sb + ALO + (wrow + lrow) * RS + lcol;
    const uint32_t bHiB = sb + BHI + (wcol + lrow) * RS + lcol;
    const uint32_t bLoB = sb + BLO + (wcol + lrow) * RS + lcol;

    for (int L = Lbeg; L < Lend; ++L) {
        int ti, tj;
        if (L < nA) { ti = a;  tj = a + L; }
        else        { ti = ap; tj = ap + (L - nA); }

        __syncthreads();   // previous tile's scans done: safe to overwrite S/A/B

        // ---- load tiles (cp.async; A reloaded each tile — stateless) ----
        {
            const uint4* ah = (const uint4*)(g_hi + (size_t)(b * NN + ti * 128) * CC);
            const uint4* al = (const uint4*)(g_lo + (size_t)(b * NN + ti * 128) * CC);
            const uint4* bh = (const uint4*)(g_hi + (size_t)(b * NN + tj * 128) * CC);
            const uint4* bl = (const uint4*)(g_lo + (size_t)(b * NN + tj * 128) * CC);
#pragma unroll
            for (int k = 0; k < 4; ++k) {
                int i = tid + k * 256;        // 0..1023: 128 rows x 8 segs
                int r = i >> 3, seg = i & 7;
                int o = r * RS + seg * 16;
                cp16(sb + AHI + o, ah + r * 8 + seg);
                cp16(sb + ALO + o, al + r * 8 + seg);
                cp16(sb + BHI + o, bh + r * 8 + seg);
                cp16(sb + BLO + o, bl + r * 8 + seg);
            }
            if (tid < 32)      cp16(sb + XXA + tid * 16, g_xx + b * NN + ti * 128 + tid * 4);
            else if (tid < 64) cp16(sb + XXB + (tid - 32) * 16,
                                    g_xx + b * NN + tj * 128 + (tid - 32) * 4);
            CP_COMMIT();
        }
        CP_WAIT0();
        __syncthreads();

        // ---- MMA: 128x128 tile, 3-pass bf16 split (R5 verbatim) ----
        float acc[2][8][4];
#pragma unroll
        for (int i = 0; i < 2; ++i)
#pragma unroll
            for (int j = 0; j < 8; ++j)
#pragma unroll
                for (int k = 0; k < 4; ++k) acc[i][j][k] = 0.f;

#pragma unroll
        for (int ks = 0; ks < 4; ++ks) {
            const int ko = ks * 32;    // bytes: 16 bf16 per k-step
            uint32_t aH[2][4], aL[2][4];
#pragma unroll
            for (int m2 = 0; m2 < 2; ++m2) {
                ldsm4(aH[m2][0], aH[m2][1], aH[m2][2], aH[m2][3], aHiB + m2 * 16 * RS + ko);
                ldsm4(aL[m2][0], aL[m2][1], aL[m2][2], aL[m2][3], aLoB + m2 * 16 * RS + ko);
            }
#pragma unroll
            for (int ng = 0; ng < 4; ++ng) {
                uint32_t h0, h1, h2, h3, l0, l1, l2, l3;
                ldsm4(h0, h1, h2, h3, bHiB + ng * 16 * RS + ko);
                ldsm4(l0, l1, l2, l3, bLoB + ng * 16 * RS + ko);
#pragma unroll
                for (int m2 = 0; m2 < 2; ++m2) {
                    mma16816(acc[m2][ng * 2],     aH[m2], h0, h2);
                    mma16816(acc[m2][ng * 2 + 1], aH[m2], h1, h3);
                    mma16816(acc[m2][ng * 2],     aH[m2], l0, l2);
                    mma16816(acc[m2][ng * 2 + 1], aH[m2], l1, l3);
                    mma16816(acc[m2][ng * 2],     aL[m2], h0, h2);
                    mma16816(acc[m2][ng * 2 + 1], aL[m2], h1, h3);
                }
            }
        }
        __syncthreads();   // tiles consumed; S may overwrite

        // ---- spill S[q][m] ----
        {
            const int r  = lane >> 2;
            const int cp = (lane & 3) * 2;
#pragma unroll
            for (int m2 = 0; m2 < 2; ++m2)
#pragma unroll
                for (int j = 0; j < 8; ++j) {
                    int row = wrow + m2 * 16 + r;
                    int col = wcol + j * 8 + cp;
                    S[row * SROW + col]           = acc[m2][j][0];
                    S[row * SROW + col + 1]       = acc[m2][j][1];
                    S[(row + 8) * SROW + col]     = acc[m2][j][2];
                    S[(row + 8) * SROW + col + 1] = acc[m2][j][3];
                }
        }
        __syncthreads();

        // ---- scans (R5 verbatim: per-tile lists, per-tile dumps) ----
        float val9[9];
        int   idx9[9];
#pragma unroll
        for (int k = 0; k < 9; ++k) { val9[k] = -3.4e38f; idx9[k] = 0x7FFFFFFF; }

        if (tid < 128) {
            // row scan: query = ti*128 + tid, candidates = block tj -> slot tj
            const float* srow = &S[tid * SROW];
            const int base = tj * 128;
            for (int m = 0; m < 128; ++m) {
                float v = fmaf(2.f, srow[m], -xxB[m]);
                INS9(v, base + m);
            }
            size_t o = ((size_t)(b * NN + ti * 128 + tid) * 16 + tj) * 9;
#pragma unroll
            for (int k = 0; k < 9; ++k) { g_pv[o + k] = val9[k]; g_pi[o + k] = idx9[k]; }
        } else if (ti != tj) {
            // col scan: query = tj*128 + (tid-128), candidates = block ti -> slot ti
            const int q = tid - 128;
            const int base = ti * 128;
            for (int m = 0; m < 128; ++m) {
                float v = fmaf(2.f, S[m * SROW + q], -xxA[m]);
                INS9(v, base + m);
            }
            size_t o = ((size_t)(b * NN + tj * 128 + q) * 16 + ti) * 9;
#pragma unroll
            for (int k = 0; k < 9; ++k) { g_pv[o + k] = val9[k]; g_pi[o + k] = idx9[k]; }
        }
    }
}

// ---------------------------------------------------------------------------
// Merge: per query, merge 16 sorted partial top-9 lists. (R5 verbatim)
// Lists sorted (val desc, idx asc); lexicographic insert is order-free.
// ---------------------------------------------------------------------------
__global__ void merge_kernel() {
    int q = blockIdx.x * 256 + threadIdx.x;      // 0 .. BB*NN-1
    const float* pv = g_pv + (size_t)q * 144;
    const int*   pi = g_pi + (size_t)q * 144;
    float val9[9];
    int   idx9[9];
#pragma unroll
    for (int k = 0; k < 9; ++k) { val9[k] = -3.4e38f; idx9[k] = 0x7FFFFFFF; }
    for (int s = 0; s < 16; ++s) {
#pragma unroll
        for (int k = 0; k < 9; ++k) {
            float v = pv[s * 9 + k];
            int  ii = pi[s * 9 + k];
            if (!(v > val9[8] || (v == val9[8] && ii < idx9[8]))) break;  // sorted desc
            INS9(v, ii);
        }
    }
    int* gout = &g_idx[(size_t)q * 8];
#pragma unroll
    for (int k = 0; k < 8; ++k) gout[k] = idx9[k + 1];   // rank 0 = self
}

// ---------------------------------------------------------------------------
// Output assembly (R5 verbatim):
// out[b,c,n] = x[b,c,n];  out[b,c,N+n] = mean_k x[b,c,idx[b,n,k]]
// ---------------------------------------------------------------------------
__global__ void gather_kernel(const float* __restrict__ x, float* __restrict__ out) {
    __shared__ float row[NN];
    int b = blockIdx.x >> 6;
    int c = blockIdx.x & 63;
    const float* xr = x + (b * CC + c) * NN;
    for (int n = threadIdx.x; n < NN; n += blockDim.x) row[n] = xr[n];
    __syncthreads();
    const int4* gi = (const int4*)(g_idx + (size_t)b * NN * 8);
    float* o = out + (size_t)(b * CC + c) * (2 * NN);
    for (int n = threadIdx.x; n < NN; n += blockDim.x) {
        o[n] = row[n];
        int4 i0 = gi[n * 2];
        int4 i1 = gi[n * 2 + 1];
        float s = row[i0.x] + row[i0.y] + row[i0.z] + row[i0.w]
                + row[i1.x] + row[i1.y] + row[i1.z] + row[i1.w];
        o[NN + n] = s * 0.125f;
    }
}

// ---------------------------------------------------------------------------
extern "C" void kernel_launch(void* const* d_in, const int* in_sizes, int n_in,
                              void* d_out, int out_size) {
    (void)in_sizes; (void)n_in; (void)out_size;
    const float* x = (const float*)d_in[0];
    float* out = (float*)d_out;

    prep_kernel<<<dim3(16, 16), 128>>>(x);

    cudaFuncSetAttribute(knn_kernel, cudaFuncAttributeMaxDynamicSharedMemorySize, SM_TOTAL);
    knn_kernel<<<dim3(16, 16), 256, SM_TOTAL>>>();   // 16 = 8 pairs x 2 halves

    merge_kernel<<<(BB * NN) / 256, 256>>>();

    gather_kernel<<<BB * CC, 256>>>(x, out);
}

// round 17
// speedup vs baseline: 1.1891x; 1.1891x over previous
#include <cuda_runtime.h>
#include <cuda_bf16.h>
#include <cstdint>

#define BB 16
#define CC 64
#define NN 2048
#define RS 144     // bf16 tile row stride (bytes): 128 data + 16 pad
#define SROW 129   // fp32 score row stride (words)
#define NTILE 136  // 16*17/2 upper-triangle tiles

// ---------------- scratch (no allocation allowed) ----------------
__device__ __nv_bfloat16 g_hi[BB * NN * CC];   // [b][n][c]
__device__ __nv_bfloat16 g_lo[BB * NN * CC];
__device__ float         g_xx[BB * NN];
__device__ float         g_pv[(size_t)BB * NN * 16 * 9];   // partial top-9 vals
__device__ int           g_pi[(size_t)BB * NN * 16 * 9];   // partial top-9 idx
__device__ int           g_idx[BB * NN * 8];

// smem layout (bytes) — identical to R5
#define AHI 0
#define ALO (AHI + 128 * RS)       // 18432
#define BHI (ALO + 128 * RS)       // 36864
#define BLO (BHI + 128 * RS)       // 55296
#define XXA (BLO + 128 * RS)       // 73728
#define XXB (XXA + 512)            // 74240
#define SM_TOTAL (XXB + 512)       // 74752;  S[128][129] fp32 aliases [0, 66048)

__device__ __forceinline__ uint32_t smem_u32(const void* p) {
    uint32_t a;
    asm("{ .reg .u64 t; cvta.to.shared.u64 t, %1; cvt.u32.u64 %0, t; }" : "=r"(a) : "l"(p));
    return a;
}
__device__ __forceinline__ void ldsm4(uint32_t& r0, uint32_t& r1, uint32_t& r2, uint32_t& r3,
                                      uint32_t addr) {
    asm volatile("ldmatrix.sync.aligned.m8n8.x4.shared.b16 {%0,%1,%2,%3}, [%4];"
                 : "=r"(r0), "=r"(r1), "=r"(r2), "=r"(r3) : "r"(addr));
}
__device__ __forceinline__ void mma16816(float* c, const uint32_t* a, uint32_t b0, uint32_t b1) {
    asm volatile(
        "mma.sync.aligned.m16n8k16.row.col.f32.bf16.bf16.f32 "
        "{%0,%1,%2,%3}, {%4,%5,%6,%7}, {%8,%9}, {%0,%1,%2,%3};"
        : "+f"(c[0]), "+f"(c[1]), "+f"(c[2]), "+f"(c[3])
        : "r"(a[0]), "r"(a[1]), "r"(a[2]), "r"(a[3]), "r"(b0), "r"(b1));
}
__device__ __forceinline__ void cp16(uint32_t dst, const void* src) {
    asm volatile("cp.async.cg.shared.global [%0], [%1], 16;" :: "r"(dst), "l"(src));
}
#define CP_COMMIT() asm volatile("cp.async.commit_group;" ::: "memory")
#define CP_WAIT0()  asm volatile("cp.async.wait_group 0;" ::: "memory")

// lexicographic top-9 insert: (val desc, idx asc) == top_k semantics, order-free
#define INS9(v, ii)                                                            \
    if ((v) > val9[8] || ((v) == val9[8] && (ii) < idx9[8])) {                 \
        val9[8] = (v); idx9[8] = (ii);                                         \
        _Pragma("unroll")                                                      \
        for (int k = 8; k > 0; --k) {                                          \
            if (val9[k] > val9[k - 1] ||                                       \
                (val9[k] == val9[k - 1] && idx9[k] < idx9[k - 1])) {           \
                float tv = val9[k]; val9[k] = val9[k - 1]; val9[k - 1] = tv;   \
                int ti_ = idx9[k]; idx9[k] = idx9[k - 1]; idx9[k - 1] = ti_;   \
            }                                                                  \
        }                                                                      \
    }

// ---------------------------------------------------------------------------
// Prep: hi/lo bf16 split, transposed [b][n][c] + fp32 norms.  (R5 verbatim)
// ---------------------------------------------------------------------------
__global__ void prep_kernel(const float* __restrict__ x) {
    int b = blockIdx.y;
    int n = blockIdx.x * 128 + threadIdx.x;
    const float* xp = x + b * CC * NN + n;
    __nv_bfloat162 hi2[32], lo2[32];
    float s = 0.f;
#pragma unroll
    for (int c2 = 0; c2 < 32; ++c2) {
        float v0 = xp[(2 * c2) * NN];
        float v1 = xp[(2 * c2 + 1) * NN];
        s = fmaf(v0, v0, s);
        s = fmaf(v1, v1, s);
        __nv_bfloat16 h0 = __float2bfloat16(v0);
        __nv_bfloat16 h1 = __float2bfloat16(v1);
        float r0 = v0 - __bfloat162float(h0);
        float r1 = v1 - __bfloat162float(h1);
        hi2[c2] = __halves2bfloat162(h0, h1);
        lo2[c2] = __halves2bfloat162(__float2bfloat16(r0), __float2bfloat16(r1));
    }
    g_xx[b * NN + n] = s;
    size_t rowo = (size_t)(b * NN + n) * CC;
    uint4* dh = (uint4*)(g_hi + rowo);
    uint4* dl = (uint4*)(g_lo + rowo);
    const uint4* sh = (const uint4*)hi2;
    const uint4* sl = (const uint4*)lo2;
#pragma unroll
    for (int i = 0; i < 8; ++i) { dh[i] = sh[i]; dl[i] = sl[i]; }
}

// ---------------------------------------------------------------------------
// KNN tile kernel: one CTA = one upper-triangle 128x128 tile (ti <= tj).
// R5 structure verbatim (single-tile stateless CTAs, natural wave-stagger);
// only the tile loads are cp.async (LDGSTS) instead of LDG+STS.
// ---------------------------------------------------------------------------
__global__ void __launch_bounds__(256, 2) knn_kernel() {
    extern __shared__ char sm[];
    const uint32_t sb = smem_u32(sm);
    const int tid  = threadIdx.x;
    const int lane = tid & 31;
    const int w    = tid >> 5;
    const int wrow = (w >> 1) * 32;       // warp query-row offset (0..96)
    const int wcol = (w & 1) * 64;        // warp candidate-col offset (0/64)
    const int b    = blockIdx.y;

    // decode upper-triangle tile (ti, tj)
    int t = blockIdx.x, ti = 0;
    while (t >= 16 - ti) { t -= 16 - ti; ++ti; }
    const int tj = ti + t;

    float* S   = (float*)sm;              // aliases A/B tiles after MMA
    float* xxA = (float*)(sm + XXA);
    float* xxB = (float*)(sm + XXB);

    // ---- load tiles via cp.async ----
    {
        const uint4* ah = (const uint4*)(g_hi + (size_t)(b * NN + ti * 128) * CC);
        const uint4* al = (const uint4*)(g_lo + (size_t)(b * NN + ti * 128) * CC);
        const uint4* bh = (const uint4*)(g_hi + (size_t)(b * NN + tj * 128) * CC);
        const uint4* bl = (const uint4*)(g_lo + (size_t)(b * NN + tj * 128) * CC);
#pragma unroll
        for (int k = 0; k < 4; ++k) {
            int i = tid + k * 256;            // 0..1023: 128 rows x 8 segs
            int r = i >> 3, seg = i & 7;
            int o = r * RS + seg * 16;
            cp16(sb + AHI + o, ah + r * 8 + seg);
            cp16(sb + ALO + o, al + r * 8 + seg);
            cp16(sb + BHI + o, bh + r * 8 + seg);
            cp16(sb + BLO + o, bl + r * 8 + seg);
        }
        if (tid < 32)      cp16(sb + XXA + tid * 16, g_xx + b * NN + ti * 128 + tid * 4);
        else if (tid < 64) cp16(sb + XXB + (tid - 32) * 16,
                                g_xx + b * NN + tj * 128 + (tid - 32) * 4);
        CP_COMMIT();
    }
    CP_WAIT0();
    __syncthreads();

    // ---- MMA: 128x128 tile, 3-pass bf16 split (R5 verbatim) ----
    float acc[2][8][4];
#pragma unroll
    for (int i = 0; i < 2; ++i)
#pragma unroll
        for (int j = 0; j < 8; ++j)
#pragma unroll
            for (int k = 0; k < 4; ++k) acc[i][j][k] = 0.f;

    const int lrow = lane & 15;
    const int lcol = (lane >> 4) * 16;
    const uint32_t aHiB = sb + AHI + (wrow + lrow) * RS + lcol;
    const uint32_t aLoB = sb + ALO + (wrow + lrow) * RS + lcol;
    const uint32_t bHiB = sb + BHI + (wcol + lrow) * RS + lcol;
    const uint32_t bLoB = sb + BLO + (wcol + lrow) * RS + lcol;

#pragma unroll
    for (int ks = 0; ks < 4; ++ks) {
        const int ko = ks * 32;    // bytes: 16 bf16 per k-step
        uint32_t aH[2][4], aL[2][4];
#pragma unroll
        for (int m2 = 0; m2 < 2; ++m2) {
            ldsm4(aH[m2][0], aH[m2][1], aH[m2][2], aH[m2][3], aHiB + m2 * 16 * RS + ko);
            ldsm4(aL[m2][0], aL[m2][1], aL[m2][2], aL[m2][3], aLoB + m2 * 16 * RS + ko);
        }
#pragma unroll
        for (int ng = 0; ng < 4; ++ng) {
            uint32_t h0, h1, h2, h3, l0, l1, l2, l3;
            ldsm4(h0, h1, h2, h3, bHiB + ng * 16 * RS + ko);
            ldsm4(l0, l1, l2, l3, bLoB + ng * 16 * RS + ko);
#pragma unroll
            for (int m2 = 0; m2 < 2; ++m2) {
                mma16816(acc[m2][ng * 2],     aH[m2], h0, h2);
                mma16816(acc[m2][ng * 2 + 1], aH[m2], h1, h3);
                mma16816(acc[m2][ng * 2],     aH[m2], l0, l2);
                mma16816(acc[m2][ng * 2 + 1], aH[m2], l1, l3);
                mma16816(acc[m2][ng * 2],     aL[m2], h0, h2);
                mma16816(acc[m2][ng * 2 + 1], aL[m2], h1, h3);
            }
        }
    }
    __syncthreads();   // tiles consumed; S may overwrite

    // ---- spill S[q][m] (R5 verbatim) ----
    {
        const int r  = lane >> 2;
        const int cp = (lane & 3) * 2;
#pragma unroll
        for (int m2 = 0; m2 < 2; ++m2)
#pragma unroll
            for (int j = 0; j < 8; ++j) {
                int row = wrow + m2 * 16 + r;
                int col = wcol + j * 8 + cp;
                S[row * SROW + col]           = acc[m2][j][0];
                S[row * SROW + col + 1]       = acc[m2][j][1];
                S[(row + 8) * SROW + col]     = acc[m2][j][2];
                S[(row + 8) * SROW + col + 1] = acc[m2][j][3];
            }
    }
    __syncthreads();

    // ---- scans (R5 verbatim) ----
    float val9[9];
    int   idx9[9];
#pragma unroll
    for (int k = 0; k < 9; ++k) { val9[k] = -3.4e38f; idx9[k] = 0x7FFFFFFF; }

    if (tid < 128) {
        // row scan: query = ti*128 + tid, candidates = block tj -> slot tj
        const float* srow = &S[tid * SROW];
        const int base = tj * 128;
        for (int m = 0; m < 128; ++m) {
            float v = fmaf(2.f, srow[m], -xxB[m]);
            INS9(v, base + m);
        }
        size_t o = ((size_t)(b * NN + ti * 128 + tid) * 16 + tj) * 9;
#pragma unroll
        for (int k = 0; k < 9; ++k) { g_pv[o + k] = val9[k]; g_pi[o + k] = idx9[k]; }
    } else if (ti != tj) {
        // col scan: query = tj*128 + (tid-128), candidates = block ti -> slot ti
        const int q = tid - 128;
        const int base = ti * 128;
        for (int m = 0; m < 128; ++m) {
            float v = fmaf(2.f, S[m * SROW + q], -xxA[m]);
            INS9(v, base + m);
        }
        size_t o = ((size_t)(b * NN + tj * 128 + q) * 16 + ti) * 9;
#pragma unroll
        for (int k = 0; k < 9; ++k) { g_pv[o + k] = val9[k]; g_pi[o + k] = idx9[k]; }
    }
}

// ---------------------------------------------------------------------------
// Merge: per query, merge 16 sorted partial top-9 lists. (R5 verbatim)
// ---------------------------------------------------------------------------
__global__ void merge_kernel() {
    int q = blockIdx.x * 256 + threadIdx.x;      // 0 .. BB*NN-1
    const float* pv = g_pv + (size_t)q * 144;
    const int*   pi = g_pi + (size_t)q * 144;
    float val9[9];
    int   idx9[9];
#pragma unroll
    for (int k = 0; k < 9; ++k) { val9[k] = -3.4e38f; idx9[k] = 0x7FFFFFFF; }
    for (int s = 0; s < 16; ++s) {
#pragma unroll
        for (int k = 0; k < 9; ++k) {
            float v = pv[s * 9 + k];
            int  ii = pi[s * 9 + k];
            if (!(v > val9[8] || (v == val9[8] && ii < idx9[8]))) break;  // sorted desc
            INS9(v, ii);
        }
    }
    int* gout = &g_idx[(size_t)q * 8];
#pragma unroll
    for (int k = 0; k < 8; ++k) gout[k] = idx9[k + 1];   // rank 0 = self
}

// ---------------------------------------------------------------------------
// Output assembly (R5 verbatim):
// out[b,c,n] = x[b,c,n];  out[b,c,N+n] = mean_k x[b,c,idx[b,n,k]]
// ---------------------------------------------------------------------------
__global__ void gather_kernel(const float* __restrict__ x, float* __restrict__ out) {
    __shared__ float row[NN];
    int b = blockIdx.x >> 6;
    int c = blockIdx.x & 63;
    const float* xr = x + (b * CC + c) * NN;
    for (int n = threadIdx.x; n < NN; n += blockDim.x) row[n] = xr[n];
    __syncthreads();
    const int4* gi = (const int4*)(g_idx + (size_t)b * NN * 8);
    float* o = out + (size_t)(b * CC + c) * (2 * NN);
    for (int n = threadIdx.x; n < NN; n += blockDim.x) {
        o[n] = row[n];
        int4 i0 = gi[n * 2];
        int4 i1 = gi[n * 2 + 1];
        float s = row[i0.x] + row[i0.y] + row[i0.z] + row[i0.w]
                + row[i1.x] + row[i1.y] + row[i1.z] + row[i1.w];
        o[NN + n] = s * 0.125f;
    }
}

// ---------------------------------------------------------------------------
extern "C" void kernel_launch(void* const* d_in, const int* in_sizes, int n_in,
                              void* d_out, int out_size) {
    (void)in_sizes; (void)n_in; (void)out_size;
    const float* x = (const float*)d_in[0];
    float* out = (float*)d_out;

    prep_kernel<<<dim3(16, 16), 128>>>(x);

    cudaFuncSetAttribute(knn_kernel, cudaFuncAttributeMaxDynamicSharedMemorySize, SM_TOTAL);
    knn_kernel<<<dim3(NTILE, BB), 256, SM_TOTAL>>>();

    merge_kernel<<<(BB * NN) / 256, 256>>>();

    gather_kernel<<<BB * CC, 256>>>(x, out);
}